// round 5
// baseline (speedup 1.0000x reference)
#include <cuda_runtime.h>
#include <cstdint>

#define N_NODES 100000
#define F_IN    512
#define MAX_E   3200000
#define SCAN_B  1024
#define SCAN_G  ((N_NODES + SCAN_B - 1) / SCAN_B)   // 98

// -------- device scratch --------
__device__ int                g_is64;
__device__ unsigned long long g_pack[MAX_E];   // src | dst<<20 | rank<<40
__device__ int                g_csr[MAX_E];    // src ids sorted by dst
__device__ int                g_deg[N_NODES];
__device__ int                g_ptr[N_NODES + 1];  // block-local prefix; +boff = global
__device__ int                g_bsum[SCAN_G];
__device__ int                g_boff[SCAN_G];
__device__ float              g_dinv[N_NODES];
__device__ float              g_h1[N_NODES * 16];  // (x @ W1) * dinv  (pre-scaled)
__device__ float              g_h2[N_NODES * 8];   // h2 * dinv (pre-scaled, padded)

__device__ __forceinline__ int ptr_at(int n) {
    return (n == N_NODES) ? g_ptr[N_NODES] : g_ptr[n] + g_boff[n >> 10];
}

// -------- init: zero deg; block 0 detects int64 vs int32 --------
__global__ void k_init(const unsigned int* ei) {
    int i = blockIdx.x * blockDim.x + threadIdx.x;
    if (i < N_NODES) g_deg[i] = 0;
    if (blockIdx.x == 0) {
        __shared__ int nz;
        if (threadIdx.x == 0) nz = 0;
        __syncthreads();
        for (int k = threadIdx.x; k < 2048; k += blockDim.x)
            if (ei[2 * k + 1] != 0u) nz = 1;
        __syncthreads();
        if (threadIdx.x == 0) g_is64 = (nz == 0) ? 1 : 0;
    }
}

// convert edges: pack (src,dst,rank) into u64; degree histogram
__global__ void k_convert(const void* ei, int E) {
    int e = blockIdx.x * blockDim.x + threadIdx.x;
    if (e >= E) return;
    unsigned int s, d;
    if (g_is64) {
        const long long* p = (const long long*)ei;
        s = (unsigned int)p[e];
        d = (unsigned int)p[E + e];
    } else {
        const unsigned int* p = (const unsigned int*)ei;
        s = p[e];
        d = p[E + e];
    }
    unsigned int r = (unsigned int)atomicAdd(&g_deg[d], 1);
    g_pack[e] = (unsigned long long)s | ((unsigned long long)d << 20)
              | ((unsigned long long)r << 40);
}

// scan phase 1: block-local exclusive prefix + block sums + dinv
__global__ void __launch_bounds__(SCAN_B) k_scan1() {
    __shared__ int s[SCAN_B];
    int t = threadIdx.x;
    int n = blockIdx.x * SCAN_B + t;
    int dg = (n < N_NODES) ? g_deg[n] : 0;
    s[t] = dg;
    __syncthreads();
#pragma unroll
    for (int off = 1; off < SCAN_B; off <<= 1) {
        int v = (t >= off) ? s[t - off] : 0;
        __syncthreads();
        s[t] += v;
        __syncthreads();
    }
    if (n < N_NODES) {
        g_ptr[n]  = s[t] - dg;
        g_dinv[n] = rsqrtf((float)(dg + 1));
    }
    if (t == SCAN_B - 1) g_bsum[blockIdx.x] = s[t];
}

// scan phase 2: parallel scan of 98 block sums
__global__ void __launch_bounds__(128) k_scan2() {
    __shared__ int s[128];
    int t = threadIdx.x;
    int v = (t < SCAN_G) ? g_bsum[t] : 0;
    s[t] = v;
    __syncthreads();
#pragma unroll
    for (int off = 1; off < 128; off <<= 1) {
        int u = (t >= off) ? s[t - off] : 0;
        __syncthreads();
        s[t] += u;
        __syncthreads();
    }
    if (t < SCAN_G) g_boff[t] = s[t] - v;  // exclusive
    if (t == 127)   g_ptr[N_NODES] = s[127];
}

// atomic-free scatter into CSR (boff folded inline)
__global__ void k_scatter(int E) {
    int e = blockIdx.x * blockDim.x + threadIdx.x;
    if (e >= E) return;
    unsigned long long p = g_pack[e];
    int s = (int)(p & 0xFFFFFu);
    int d = (int)((p >> 20) & 0xFFFFFu);
    int r = (int)(p >> 40);
    g_csr[g_ptr[d] + g_boff[d >> 10] + r] = s;
}

// -------- GEMM: hs1 = (x @ W1) * dinv;  2 rows per thread, FFMA2 --------
#define KC 16
#define XS_STRIDE 20   // floats per staged row (16 + pad, float4-aligned)

__global__ void __launch_bounds__(256) k_gemm1(const float* __restrict__ x,
                                               const float* __restrict__ W1) {
    __shared__ float xs[512 * XS_STRIDE];   // 40 KB
    __shared__ float wc[KC * 16];           // 1 KB
    int t = threadIdx.x;
    int rbase = blockIdx.x * 512;

    unsigned long long acc[16];   // [0..7] row0 cols, [8..15] row1 cols
#pragma unroll
    for (int j = 0; j < 16; j++) acc[j] = 0ull;

    for (int kb = 0; kb < F_IN; kb += KC) {
        __syncthreads();
        // stage x chunk: 512 rows x 16 floats (4 float4 per row)
#pragma unroll
        for (int i = 0; i < 8; i++) {
            int flat = t + 256 * i;        // float4 index
            int row  = flat >> 2;          // 4 float4 per row
            int k4   = flat & 3;
            float4 v = make_float4(0.f, 0.f, 0.f, 0.f);
            int gr = rbase + row;
            if (gr < N_NODES)
                v = *(const float4*)(x + (size_t)gr * F_IN + kb + k4 * 4);
            *(float4*)(xs + row * XS_STRIDE + k4 * 4) = v;
        }
        // stage W chunk: 16 rows x 16 = 256 floats
        if (t < 64)
            *(float4*)(wc + t * 4) = *(const float4*)(W1 + kb * 16 + t * 4);
        __syncthreads();

#pragma unroll
        for (int k4 = 0; k4 < 4; k4++) {
            float4 xa = *(float4*)(xs + t * XS_STRIDE + k4 * 4);
            float4 xb = *(float4*)(xs + (t + 256) * XS_STRIDE + k4 * 4);
            float xav[4] = {xa.x, xa.y, xa.z, xa.w};
            float xbv[4] = {xb.x, xb.y, xb.z, xb.w};
#pragma unroll
            for (int c = 0; c < 4; c++) {
                int k = k4 * 4 + c;
                unsigned long long x0, x1;
                asm("mov.b64 %0, {%1,%1};" : "=l"(x0) : "f"(xav[c]));
                asm("mov.b64 %0, {%1,%1};" : "=l"(x1) : "f"(xbv[c]));
                const unsigned long long* wr =
                    (const unsigned long long*)(wc + k * 16);
#pragma unroll
                for (int j = 0; j < 8; j++) {
                    unsigned long long w = wr[j];
                    asm("fma.rn.f32x2 %0, %1, %2, %0;"
                        : "+l"(acc[j]) : "l"(x0), "l"(w));
                    asm("fma.rn.f32x2 %0, %1, %2, %0;"
                        : "+l"(acc[8 + j]) : "l"(x1), "l"(w));
                }
            }
        }
    }

#pragma unroll
    for (int half = 0; half < 2; half++) {
        int r = rbase + t + half * 256;
        if (r < N_NODES) {
            float di = g_dinv[r];
            float4* hp = (float4*)(g_h1 + (size_t)r * 16);
#pragma unroll
            for (int q = 0; q < 4; q++) {
                float lo0, hi0, lo1, hi1;
                asm("mov.b64 {%0,%1}, %2;" : "=f"(lo0), "=f"(hi0)
                    : "l"(acc[half * 8 + 2 * q]));
                asm("mov.b64 {%0,%1}, %2;" : "=f"(lo1), "=f"(hi1)
                    : "l"(acc[half * 8 + 2 * q + 1]));
                hp[q] = make_float4(lo0 * di, hi0 * di, lo1 * di, hi1 * di);
            }
        }
    }
}

// -------- layer 1 aggregate (pure gather-sum of hs1) + layer 2 transform --------
__global__ void __launch_bounds__(256) k_agg1x(const float* __restrict__ b1,
                                               const float* __restrict__ W2) {
    __shared__ float sW[128];  // [0:112) W2 row-major [16,7], [112:128) b1
    int t = threadIdx.x;
    if (t < 112) sW[t] = W2[t];
    else if (t < 128) sW[t] = b1[t - 112];
    __syncthreads();

    int n = blockIdx.x * blockDim.x + t;
    if (n >= N_NODES) return;

    float di = g_dinv[n];
    float acc[16];
    {
        const float4* hp = (const float4*)(g_h1 + (size_t)n * 16);
#pragma unroll
        for (int q = 0; q < 4; q++) {
            float4 v = hp[q];   // self term: hs1[n]
            acc[4 * q + 0] = v.x;
            acc[4 * q + 1] = v.y;
            acc[4 * q + 2] = v.z;
            acc[4 * q + 3] = v.w;
        }
    }
    int beg = ptr_at(n), end = ptr_at(n + 1);
    int i = beg;
    for (; i + 4 <= end; i += 4) {
        int sj[4];
#pragma unroll
        for (int j = 0; j < 4; j++) sj[j] = __ldg(&g_csr[i + j]);
        float4 rows[4][4];
#pragma unroll
        for (int j = 0; j < 4; j++) {
            const float4* q0 = (const float4*)(g_h1 + (size_t)sj[j] * 16);
#pragma unroll
            for (int q = 0; q < 4; q++) rows[j][q] = __ldg(&q0[q]);
        }
#pragma unroll
        for (int j = 0; j < 4; j++)
#pragma unroll
            for (int q = 0; q < 4; q++) {
                acc[4 * q + 0] += rows[j][q].x;
                acc[4 * q + 1] += rows[j][q].y;
                acc[4 * q + 2] += rows[j][q].z;
                acc[4 * q + 3] += rows[j][q].w;
            }
    }
    for (; i < end; i++) {
        int s0 = __ldg(&g_csr[i]);
        const float4* q0 = (const float4*)(g_h1 + (size_t)s0 * 16);
#pragma unroll
        for (int q = 0; q < 4; q++) {
            float4 a = __ldg(&q0[q]);
            acc[4 * q + 0] += a.x;
            acc[4 * q + 1] += a.y;
            acc[4 * q + 2] += a.z;
            acc[4 * q + 3] += a.w;
        }
    }
    // pre-act = di*acc + b1 ; relu ; @W2 ; store hs2 = h*di
    float v[16];
#pragma unroll
    for (int k = 0; k < 16; k++) v[k] = fmaxf(fmaf(di, acc[k], sW[112 + k]), 0.f);
    float h[7];
#pragma unroll
    for (int j = 0; j < 7; j++) {
        float s = 0.f;
#pragma unroll
        for (int k = 0; k < 16; k++) s += v[k] * sW[k * 7 + j];
        h[j] = s * di;
    }
    float4* hp = (float4*)(g_h2 + (size_t)n * 8);
    hp[0] = make_float4(h[0], h[1], h[2], h[3]);
    hp[1] = make_float4(h[4], h[5], h[6], 0.f);
}

// -------- layer 2 aggregate (pure gather-sum of hs2), writes d_out --------
__global__ void __launch_bounds__(256) k_agg2(const float* __restrict__ b2,
                                              float* __restrict__ out) {
    int n = blockIdx.x * blockDim.x + threadIdx.x;
    if (n >= N_NODES) return;
    float di = g_dinv[n];
    float acc[7];
    {
        const float4* hp = (const float4*)(g_h2 + (size_t)n * 8);
        float4 a = hp[0], b = hp[1];
        acc[0] = a.x; acc[1] = a.y; acc[2] = a.z; acc[3] = a.w;
        acc[4] = b.x; acc[5] = b.y; acc[6] = b.z;
    }
    int beg = ptr_at(n), end = ptr_at(n + 1);
    int i = beg;
    for (; i + 4 <= end; i += 4) {
        int sj[4];
#pragma unroll
        for (int j = 0; j < 4; j++) sj[j] = __ldg(&g_csr[i + j]);
        float4 r0[4], r1[4];
#pragma unroll
        for (int j = 0; j < 4; j++) {
            const float4* p0 = (const float4*)(g_h2 + (size_t)sj[j] * 8);
            r0[j] = __ldg(&p0[0]);
            r1[j] = __ldg(&p0[1]);
        }
#pragma unroll
        for (int j = 0; j < 4; j++) {
            acc[0] += r0[j].x;
            acc[1] += r0[j].y;
            acc[2] += r0[j].z;
            acc[3] += r0[j].w;
            acc[4] += r1[j].x;
            acc[5] += r1[j].y;
            acc[6] += r1[j].z;
        }
    }
    for (; i < end; i++) {
        int s0 = __ldg(&g_csr[i]);
        const float4* p0 = (const float4*)(g_h2 + (size_t)s0 * 8);
        float4 a0 = __ldg(&p0[0]), a1 = __ldg(&p0[1]);
        acc[0] += a0.x;
        acc[1] += a0.y;
        acc[2] += a0.z;
        acc[3] += a0.w;
        acc[4] += a1.x;
        acc[5] += a1.y;
        acc[6] += a1.z;
    }
    float* op = out + (size_t)n * 7;
#pragma unroll
    for (int j = 0; j < 7; j++) op[j] = fmaf(di, acc[j], __ldg(b2 + j));
}

extern "C" void kernel_launch(void* const* d_in, const int* in_sizes, int n_in,
                              void* d_out, int out_size) {
    const float* x  = (const float*)d_in[0];
    const void*  ei = d_in[1];
    const float* W1 = (const float*)d_in[2];
    const float* b1 = (const float*)d_in[3];
    const float* W2 = (const float*)d_in[4];
    const float* b2 = (const float*)d_in[5];
    int E = in_sizes[1] / 2;

    k_init<<<(N_NODES + 255) / 256, 256>>>((const unsigned int*)ei);  // 0
    k_convert<<<(E + 255) / 256, 256>>>(ei, E);                        // 1
    k_scan1<<<SCAN_G, SCAN_B>>>();                                     // 2
    k_gemm1<<<(N_NODES + 511) / 512, 256>>>(x, W1);                    // 3 <- profiled
    k_scan2<<<1, 128>>>();                                             // 4
    k_scatter<<<(E + 255) / 256, 256>>>(E);                            // 5
    k_agg1x<<<(N_NODES + 255) / 256, 256>>>(b1, W2);                   // 6
    k_agg2<<<(N_NODES + 255) / 256, 256>>>(b2, (float*)d_out);         // 7
}

// round 6
// speedup vs baseline: 1.0346x; 1.0346x over previous
#include <cuda_runtime.h>
#include <cstdint>

#define N_NODES 100000
#define F_IN    512
#define MAX_E   3200000
#define SCAN_B  1024
#define SCAN_G  ((N_NODES + SCAN_B - 1) / SCAN_B)   // 98

// -------- device scratch --------
__device__ int                g_is64;
__device__ unsigned long long g_pack[MAX_E];   // src | dst<<20 | rank<<40
__device__ int                g_csr[MAX_E];    // src ids sorted by dst
__device__ int                g_deg[N_NODES];
__device__ int                g_ptr[N_NODES + 1];  // block-local prefix; +boff = global
__device__ int                g_bsum[SCAN_G];
__device__ int                g_boff[SCAN_G];
__device__ float              g_dinv[N_NODES];
__device__ float              g_h1[N_NODES * 16];  // (x @ W1) * dinv  (pre-scaled)
__device__ float              g_h2[N_NODES * 8];   // h2 * dinv (pre-scaled, padded)

__device__ __forceinline__ int ptr_at(int n) {
    return (n == N_NODES) ? g_ptr[N_NODES] : g_ptr[n] + g_boff[n >> 10];
}

// -------- init: zero deg; block 0 detects int64 vs int32 --------
__global__ void k_init(const unsigned int* ei) {
    int i = blockIdx.x * blockDim.x + threadIdx.x;
    if (i < N_NODES) g_deg[i] = 0;
    if (blockIdx.x == 0) {
        __shared__ int nz;
        if (threadIdx.x == 0) nz = 0;
        __syncthreads();
        for (int k = threadIdx.x; k < 2048; k += blockDim.x)
            if (ei[2 * k + 1] != 0u) nz = 1;
        __syncthreads();
        if (threadIdx.x == 0) g_is64 = (nz == 0) ? 1 : 0;
    }
}

// convert edges: pack (src,dst,rank) into u64; degree histogram
__global__ void k_convert(const void* ei, int E) {
    int e = blockIdx.x * blockDim.x + threadIdx.x;
    if (e >= E) return;
    unsigned int s, d;
    if (g_is64) {
        const long long* p = (const long long*)ei;
        s = (unsigned int)p[e];
        d = (unsigned int)p[E + e];
    } else {
        const unsigned int* p = (const unsigned int*)ei;
        s = p[e];
        d = p[E + e];
    }
    unsigned int r = (unsigned int)atomicAdd(&g_deg[d], 1);
    g_pack[e] = (unsigned long long)s | ((unsigned long long)d << 20)
              | ((unsigned long long)r << 40);
}

// scan phase 1: block-local exclusive prefix + block sums + dinv
__global__ void __launch_bounds__(SCAN_B) k_scan1() {
    __shared__ int s[SCAN_B];
    int t = threadIdx.x;
    int n = blockIdx.x * SCAN_B + t;
    int dg = (n < N_NODES) ? g_deg[n] : 0;
    s[t] = dg;
    __syncthreads();
#pragma unroll
    for (int off = 1; off < SCAN_B; off <<= 1) {
        int v = (t >= off) ? s[t - off] : 0;
        __syncthreads();
        s[t] += v;
        __syncthreads();
    }
    if (n < N_NODES) {
        g_ptr[n]  = s[t] - dg;
        g_dinv[n] = rsqrtf((float)(dg + 1));
    }
    if (t == SCAN_B - 1) g_bsum[blockIdx.x] = s[t];
}

// scan phase 2: parallel scan of 98 block sums
__global__ void __launch_bounds__(128) k_scan2() {
    __shared__ int s[128];
    int t = threadIdx.x;
    int v = (t < SCAN_G) ? g_bsum[t] : 0;
    s[t] = v;
    __syncthreads();
#pragma unroll
    for (int off = 1; off < 128; off <<= 1) {
        int u = (t >= off) ? s[t - off] : 0;
        __syncthreads();
        s[t] += u;
        __syncthreads();
    }
    if (t < SCAN_G) g_boff[t] = s[t] - v;  // exclusive
    if (t == 127)   g_ptr[N_NODES] = s[127];
}

// atomic-free scatter into CSR (boff folded inline)
__global__ void k_scatter(int E) {
    int e = blockIdx.x * blockDim.x + threadIdx.x;
    if (e >= E) return;
    unsigned long long p = g_pack[e];
    int s = (int)(p & 0xFFFFFu);
    int d = (int)((p >> 20) & 0xFFFFFu);
    int r = (int)(p >> 40);
    g_csr[g_ptr[d] + g_boff[d >> 10] + r] = s;
}

// -------- GEMM: hs1 = (x @ W1) * dinv --------
// Register-tiled: block = 256 threads = 8 warps x 32 rows = 256 rows.
// Thread (rg,cg): rows rg+8r (r=0..3), cols cg*4..cg*4+3.
// k packed in FFMA2 halves (even-k lo, odd-k hi), summed at the end.
#define KC   32
#define XSTR 36   // row stride: 36 % 32 = 4 -> 8 consecutive rows hit distinct banks; 144B (16B-aligned)
#define WSTR 34   // wct row stride (even -> 8B-aligned u64 loads)

__global__ void __launch_bounds__(256) k_gemm1(const float* __restrict__ x,
                                               const float* __restrict__ W1) {
    __shared__ float xs[256 * XSTR];   // 36864 B
    __shared__ float wct[16 * WSTR];   // 2176 B, transposed W chunk [col][k]
    int t    = threadIdx.x;
    int warp = t >> 5, lane = t & 31;
    int rg   = lane >> 2, cg = lane & 3;
    int wrow = warp * 32;
    int rbase = blockIdx.x * 256;

    unsigned long long acc[4][4];   // [row r][col c], lo=even-k sum, hi=odd-k sum
#pragma unroll
    for (int r = 0; r < 4; r++)
#pragma unroll
        for (int c = 0; c < 4; c++) acc[r][c] = 0ull;

    for (int kb = 0; kb < F_IN; kb += KC) {
        __syncthreads();
        // stage x chunk: 256 rows x 32 floats, coalesced float4
#pragma unroll
        for (int i = 0; i < 8; i++) {
            int flat = t + 256 * i;    // float4 index
            int row  = flat >> 3;
            int k4   = flat & 7;
            float4 v = make_float4(0.f, 0.f, 0.f, 0.f);
            int gr = rbase + row;
            if (gr < N_NODES)
                v = *(const float4*)(x + (size_t)gr * F_IN + kb + k4 * 4);
            *(float4*)(xs + row * XSTR + k4 * 4) = v;
        }
        // stage W chunk transposed: wct[c][k] = W1[kb+k][c]
#pragma unroll
        for (int i = 0; i < 2; i++) {
            int idx = t + 256 * i;     // 512 elements
            int k = idx & 31, c = idx >> 5;
            wct[c * WSTR + k] = W1[(size_t)(kb + k) * 16 + c];
        }
        __syncthreads();

#pragma unroll 8
        for (int kk = 0; kk < KC; kk += 2) {
            unsigned long long xr[4], wv[4];
#pragma unroll
            for (int r = 0; r < 4; r++)
                xr[r] = *(const unsigned long long*)
                        (xs + (wrow + rg + 8 * r) * XSTR + kk);
#pragma unroll
            for (int c = 0; c < 4; c++)
                wv[c] = *(const unsigned long long*)
                        (wct + (cg * 4 + c) * WSTR + kk);
#pragma unroll
            for (int r = 0; r < 4; r++)
#pragma unroll
                for (int c = 0; c < 4; c++)
                    asm("fma.rn.f32x2 %0, %1, %2, %0;"
                        : "+l"(acc[r][c]) : "l"(xr[r]), "l"(wv[c]));
        }
    }

#pragma unroll
    for (int r = 0; r < 4; r++) {
        int row = rbase + wrow + rg + 8 * r;
        if (row < N_NODES) {
            float di = g_dinv[row];
            float o[4];
#pragma unroll
            for (int c = 0; c < 4; c++) {
                float lo, hi;
                asm("mov.b64 {%0,%1}, %2;" : "=f"(lo), "=f"(hi) : "l"(acc[r][c]));
                o[c] = (lo + hi) * di;
            }
            *(float4*)(g_h1 + (size_t)row * 16 + cg * 4) =
                make_float4(o[0], o[1], o[2], o[3]);
        }
    }
}

// -------- layer 1 aggregate (pure gather-sum of hs1) + layer 2 transform --------
__global__ void __launch_bounds__(256) k_agg1x(const float* __restrict__ b1,
                                               const float* __restrict__ W2) {
    __shared__ float sW[128];  // [0:112) W2 row-major [16,7], [112:128) b1
    int t = threadIdx.x;
    if (t < 112) sW[t] = W2[t];
    else if (t < 128) sW[t] = b1[t - 112];
    __syncthreads();

    int n = blockIdx.x * blockDim.x + t;
    if (n >= N_NODES) return;

    float di = g_dinv[n];
    float acc[16];
    {
        const float4* hp = (const float4*)(g_h1 + (size_t)n * 16);
#pragma unroll
        for (int q = 0; q < 4; q++) {
            float4 v = hp[q];   // self term: hs1[n]
            acc[4 * q + 0] = v.x;
            acc[4 * q + 1] = v.y;
            acc[4 * q + 2] = v.z;
            acc[4 * q + 3] = v.w;
        }
    }
    int beg = ptr_at(n), end = ptr_at(n + 1);
    int i = beg;
    for (; i + 4 <= end; i += 4) {
        int sj[4];
#pragma unroll
        for (int j = 0; j < 4; j++) sj[j] = __ldg(&g_csr[i + j]);
        float4 rows[4][4];
#pragma unroll
        for (int j = 0; j < 4; j++) {
            const float4* q0 = (const float4*)(g_h1 + (size_t)sj[j] * 16);
#pragma unroll
            for (int q = 0; q < 4; q++) rows[j][q] = __ldg(&q0[q]);
        }
#pragma unroll
        for (int j = 0; j < 4; j++)
#pragma unroll
            for (int q = 0; q < 4; q++) {
                acc[4 * q + 0] += rows[j][q].x;
                acc[4 * q + 1] += rows[j][q].y;
                acc[4 * q + 2] += rows[j][q].z;
                acc[4 * q + 3] += rows[j][q].w;
            }
    }
    for (; i < end; i++) {
        int s0 = __ldg(&g_csr[i]);
        const float4* q0 = (const float4*)(g_h1 + (size_t)s0 * 16);
#pragma unroll
        for (int q = 0; q < 4; q++) {
            float4 a = __ldg(&q0[q]);
            acc[4 * q + 0] += a.x;
            acc[4 * q + 1] += a.y;
            acc[4 * q + 2] += a.z;
            acc[4 * q + 3] += a.w;
        }
    }
    // pre-act = di*acc + b1 ; relu ; @W2 ; store hs2 = h*di
    float v[16];
#pragma unroll
    for (int k = 0; k < 16; k++) v[k] = fmaxf(fmaf(di, acc[k], sW[112 + k]), 0.f);
    float h[7];
#pragma unroll
    for (int j = 0; j < 7; j++) {
        float s = 0.f;
#pragma unroll
        for (int k = 0; k < 16; k++) s += v[k] * sW[k * 7 + j];
        h[j] = s * di;
    }
    float4* hp = (float4*)(g_h2 + (size_t)n * 8);
    hp[0] = make_float4(h[0], h[1], h[2], h[3]);
    hp[1] = make_float4(h[4], h[5], h[6], 0.f);
}

// -------- layer 2 aggregate (pure gather-sum of hs2), writes d_out --------
__global__ void __launch_bounds__(256) k_agg2(const float* __restrict__ b2,
                                              float* __restrict__ out) {
    int n = blockIdx.x * blockDim.x + threadIdx.x;
    if (n >= N_NODES) return;
    float di = g_dinv[n];
    float acc[7];
    {
        const float4* hp = (const float4*)(g_h2 + (size_t)n * 8);
        float4 a = hp[0], b = hp[1];
        acc[0] = a.x; acc[1] = a.y; acc[2] = a.z; acc[3] = a.w;
        acc[4] = b.x; acc[5] = b.y; acc[6] = b.z;
    }
    int beg = ptr_at(n), end = ptr_at(n + 1);
    int i = beg;
    for (; i + 4 <= end; i += 4) {
        int sj[4];
#pragma unroll
        for (int j = 0; j < 4; j++) sj[j] = __ldg(&g_csr[i + j]);
        float4 r0[4], r1[4];
#pragma unroll
        for (int j = 0; j < 4; j++) {
            const float4* p0 = (const float4*)(g_h2 + (size_t)sj[j] * 8);
            r0[j] = __ldg(&p0[0]);
            r1[j] = __ldg(&p0[1]);
        }
#pragma unroll
        for (int j = 0; j < 4; j++) {
            acc[0] += r0[j].x;
            acc[1] += r0[j].y;
            acc[2] += r0[j].z;
            acc[3] += r0[j].w;
            acc[4] += r1[j].x;
            acc[5] += r1[j].y;
            acc[6] += r1[j].z;
        }
    }
    for (; i < end; i++) {
        int s0 = __ldg(&g_csr[i]);
        const float4* p0 = (const float4*)(g_h2 + (size_t)s0 * 8);
        float4 a0 = __ldg(&p0[0]), a1 = __ldg(&p0[1]);
        acc[0] += a0.x;
        acc[1] += a0.y;
        acc[2] += a0.z;
        acc[3] += a0.w;
        acc[4] += a1.x;
        acc[5] += a1.y;
        acc[6] += a1.z;
    }
    float* op = out + (size_t)n * 7;
#pragma unroll
    for (int j = 0; j < 7; j++) op[j] = fmaf(di, acc[j], __ldg(b2 + j));
}

extern "C" void kernel_launch(void* const* d_in, const int* in_sizes, int n_in,
                              void* d_out, int out_size) {
    const float* x  = (const float*)d_in[0];
    const void*  ei = d_in[1];
    const float* W1 = (const float*)d_in[2];
    const float* b1 = (const float*)d_in[3];
    const float* W2 = (const float*)d_in[4];
    const float* b2 = (const float*)d_in[5];
    int E = in_sizes[1] / 2;

    k_init<<<(N_NODES + 255) / 256, 256>>>((const unsigned int*)ei);  // 0
    k_convert<<<(E + 255) / 256, 256>>>(ei, E);                        // 1
    k_scan1<<<SCAN_G, SCAN_B>>>();                                     // 2
    k_gemm1<<<(N_NODES + 255) / 256, 256>>>(x, W1);                    // 3 <- profiled
    k_scan2<<<1, 128>>>();                                             // 4
    k_scatter<<<(E + 255) / 256, 256>>>(E);                            // 5
    k_agg1x<<<(N_NODES + 255) / 256, 256>>>(b1, W2);                   // 6
    k_agg2<<<(N_NODES + 255) / 256, 256>>>(b2, (float*)d_out);         // 7
}

// round 7
// speedup vs baseline: 1.1627x; 1.1238x over previous
#include <cuda_runtime.h>
#include <cstdint>

#define N_NODES 100000
#define F_IN    512
#define MAX_E   3200000
#define SCAN_B  1024
#define SCAN_G  ((N_NODES + SCAN_B - 1) / SCAN_B)   // 98

// -------- device scratch --------
__device__ int                g_is64;
__device__ unsigned long long g_pack[MAX_E];   // src | dst<<20 | rank<<40
__device__ int                g_csr[MAX_E];    // src ids sorted by dst
__device__ int                g_deg[N_NODES];
__device__ int                g_ptr[N_NODES + 1];  // block-local prefix; +boff = global
__device__ int                g_bsum[SCAN_G];
__device__ int                g_boff[SCAN_G];
__device__ float              g_dinv[N_NODES];
__device__ float              g_h1[N_NODES * 16];  // (x @ W1) * dinv  (pre-scaled)
__device__ float              g_h2[N_NODES * 8];   // h2 * dinv (pre-scaled, padded)

__device__ __forceinline__ int ptr_at(int n) {
    return (n == N_NODES) ? g_ptr[N_NODES] : g_ptr[n] + g_boff[n >> 10];
}

// -------- init: zero deg; block 0 detects int64 vs int32 --------
__global__ void k_init(const unsigned int* ei) {
    int i = blockIdx.x * blockDim.x + threadIdx.x;
    if (i < N_NODES) g_deg[i] = 0;
    if (blockIdx.x == 0) {
        __shared__ int nz;
        if (threadIdx.x == 0) nz = 0;
        __syncthreads();
        for (int k = threadIdx.x; k < 2048; k += blockDim.x)
            if (ei[2 * k + 1] != 0u) nz = 1;
        __syncthreads();
        if (threadIdx.x == 0) g_is64 = (nz == 0) ? 1 : 0;
    }
}

// convert edges: pack (src,dst,rank) into u64; degree histogram
__global__ void k_convert(const void* ei, int E) {
    int e = blockIdx.x * blockDim.x + threadIdx.x;
    if (e >= E) return;
    unsigned int s, d;
    if (g_is64) {
        const long long* p = (const long long*)ei;
        s = (unsigned int)p[e];
        d = (unsigned int)p[E + e];
    } else {
        const unsigned int* p = (const unsigned int*)ei;
        s = p[e];
        d = p[E + e];
    }
    unsigned int r = (unsigned int)atomicAdd(&g_deg[d], 1);
    g_pack[e] = (unsigned long long)s | ((unsigned long long)d << 20)
              | ((unsigned long long)r << 40);
}

// scan phase 1: block-local exclusive prefix + block sums + dinv
__global__ void __launch_bounds__(SCAN_B) k_scan1() {
    __shared__ int s[SCAN_B];
    int t = threadIdx.x;
    int n = blockIdx.x * SCAN_B + t;
    int dg = (n < N_NODES) ? g_deg[n] : 0;
    s[t] = dg;
    __syncthreads();
#pragma unroll
    for (int off = 1; off < SCAN_B; off <<= 1) {
        int v = (t >= off) ? s[t - off] : 0;
        __syncthreads();
        s[t] += v;
        __syncthreads();
    }
    if (n < N_NODES) {
        g_ptr[n]  = s[t] - dg;
        g_dinv[n] = rsqrtf((float)(dg + 1));
    }
    if (t == SCAN_B - 1) g_bsum[blockIdx.x] = s[t];
}

// scan phase 2: parallel scan of 98 block sums
__global__ void __launch_bounds__(128) k_scan2() {
    __shared__ int s[128];
    int t = threadIdx.x;
    int v = (t < SCAN_G) ? g_bsum[t] : 0;
    s[t] = v;
    __syncthreads();
#pragma unroll
    for (int off = 1; off < 128; off <<= 1) {
        int u = (t >= off) ? s[t - off] : 0;
        __syncthreads();
        s[t] += u;
        __syncthreads();
    }
    if (t < SCAN_G) g_boff[t] = s[t] - v;  // exclusive
    if (t == 127)   g_ptr[N_NODES] = s[127];
}

// atomic-free scatter into CSR (boff folded inline)
__global__ void k_scatter(int E) {
    int e = blockIdx.x * blockDim.x + threadIdx.x;
    if (e >= E) return;
    unsigned long long p = g_pack[e];
    int s = (int)(p & 0xFFFFFu);
    int d = (int)((p >> 20) & 0xFFFFFu);
    int r = (int)(p >> 40);
    g_csr[g_ptr[d] + g_boff[d >> 10] + r] = s;
}

// -------- GEMM: hs1 = (x @ W1) * dinv --------
// cp.async depth-2 pipelined, register tile 4 rows x 4 cols per thread,
// k packed into FFMA2 halves (even-k lo, odd-k hi).
#define KC    16
#define NCHK  (F_IN / KC)   // 32
#define XSTR  20            // 80B row stride: rg*20 mod 32 all-distinct banks; 16B-aligned
#define WSTR  34            // c*34*... c stride 4 -> 136 words mod 32 = 8 -> conflict-free

__device__ __forceinline__ void cp16(uint32_t dst, const void* src, int sz) {
    asm volatile("cp.async.cg.shared.global [%0], [%1], 16, %2;"
                 :: "r"(dst), "l"(src), "r"(sz));
}
__device__ __forceinline__ void cp_commit() {
    asm volatile("cp.async.commit_group;");
}
__device__ __forceinline__ void cp_wait1() {
    asm volatile("cp.async.wait_group 1;");
}

__global__ void __launch_bounds__(256) k_gemm1(const float* __restrict__ x,
                                               const float* __restrict__ W1) {
    __shared__ float xs[2][256 * XSTR];   // 2 x 20480 B
    __shared__ float wct[2][16 * WSTR];   // 2 x 2176 B, [c][k] transposed chunks
    int t    = threadIdx.x;
    int warp = t >> 5, lane = t & 31;
    int rg   = lane >> 2, cg = lane & 3;
    int wrow = warp * 32;
    int rbase = blockIdx.x * 256;

    // thread's cp.async assignment: 4 x 16B covering 256 rows x 16 floats
    int cp_row[4], cp_k4[4];
    uint32_t cp_dst[4];
    const float* cp_src[4];
    int cp_sz[4];
#pragma unroll
    for (int i = 0; i < 4; i++) {
        int flat = t + 256 * i;
        cp_row[i] = flat >> 2;
        cp_k4[i]  = flat & 3;
        int gr = rbase + cp_row[i];
        cp_sz[i]  = (gr < N_NODES) ? 16 : 0;
        cp_src[i] = x + (size_t)((gr < N_NODES) ? gr : 0) * F_IN + cp_k4[i] * 4;
        uint32_t base;
        asm("{ .reg .u64 tmp; cvta.to.shared.u64 tmp, %1; cvt.u32.u64 %0, tmp; }"
            : "=r"(base) : "l"((void*)&xs[0][cp_row[i] * XSTR + cp_k4[i] * 4]));
        cp_dst[i] = base;
    }
    const uint32_t XBUFB = 256 * XSTR * 4;   // bytes per x buffer

    // W staging map: t covers 16k x 16c; k = t>>4, c = t&15
    int wk = t >> 4, wc = t & 15;

    // ---- prologue: stage chunks 0 and 1 ----
#pragma unroll
    for (int c0 = 0; c0 < 2; c0++) {
#pragma unroll
        for (int i = 0; i < 4; i++)
            cp16(cp_dst[i] + c0 * XBUFB, cp_src[i] + c0 * KC, cp_sz[i]);
        cp_commit();
        wct[c0][wc * WSTR + wk] = __ldg(W1 + (size_t)(c0 * KC + wk) * 16 + wc);
    }

    unsigned long long acc[4][4];
#pragma unroll
    for (int r = 0; r < 4; r++)
#pragma unroll
        for (int c = 0; c < 4; c++) acc[r][c] = 0ull;

    for (int ch = 0; ch < NCHK; ch++) {
        int buf = ch & 1;
        cp_wait1();
        __syncthreads();

        // prefetch W for chunk ch+2 into a register (latency hidden by compute)
        float wreg = 0.f;
        if (ch + 2 < NCHK)
            wreg = __ldg(W1 + (size_t)((ch + 2) * KC + wk) * 16 + wc);

        const float* xb = xs[buf];
        const float* wb = wct[buf];
#pragma unroll
        for (int kk = 0; kk < KC; kk += 2) {
            unsigned long long xr[4], wv[4];
#pragma unroll
            for (int r = 0; r < 4; r++)
                xr[r] = *(const unsigned long long*)
                        (xb + (wrow + rg + 8 * r) * XSTR + kk);
#pragma unroll
            for (int c = 0; c < 4; c++)
                wv[c] = *(const unsigned long long*)
                        (wb + (cg * 4 + c) * WSTR + kk);
#pragma unroll
            for (int r = 0; r < 4; r++)
#pragma unroll
                for (int c = 0; c < 4; c++)
                    asm("fma.rn.f32x2 %0, %1, %2, %0;"
                        : "+l"(acc[r][c]) : "l"(xr[r]), "l"(wv[c]));
        }
        __syncthreads();

        if (ch + 2 < NCHK) {
            wct[buf][wc * WSTR + wk] = wreg;
#pragma unroll
            for (int i = 0; i < 4; i++)
                cp16(cp_dst[i] + buf * XBUFB, cp_src[i] + (ch + 2) * KC, cp_sz[i]);
            cp_commit();
        }
    }

#pragma unroll
    for (int r = 0; r < 4; r++) {
        int row = rbase + wrow + rg + 8 * r;
        if (row < N_NODES) {
            float di = g_dinv[row];
            float o[4];
#pragma unroll
            for (int c = 0; c < 4; c++) {
                float lo, hi;
                asm("mov.b64 {%0,%1}, %2;" : "=f"(lo), "=f"(hi) : "l"(acc[r][c]));
                o[c] = (lo + hi) * di;
            }
            *(float4*)(g_h1 + (size_t)row * 16 + cg * 4) =
                make_float4(o[0], o[1], o[2], o[3]);
        }
    }
}

// -------- layer 1 aggregate (pure gather-sum of hs1) + layer 2 transform --------
__global__ void __launch_bounds__(256) k_agg1x(const float* __restrict__ b1,
                                               const float* __restrict__ W2) {
    __shared__ float sW[128];  // [0:112) W2 row-major [16,7], [112:128) b1
    int t = threadIdx.x;
    if (t < 112) sW[t] = W2[t];
    else if (t < 128) sW[t] = b1[t - 112];
    __syncthreads();

    int n = blockIdx.x * blockDim.x + t;
    if (n >= N_NODES) return;

    float di = g_dinv[n];
    float acc[16];
    {
        const float4* hp = (const float4*)(g_h1 + (size_t)n * 16);
#pragma unroll
        for (int q = 0; q < 4; q++) {
            float4 v = hp[q];   // self term: hs1[n]
            acc[4 * q + 0] = v.x;
            acc[4 * q + 1] = v.y;
            acc[4 * q + 2] = v.z;
            acc[4 * q + 3] = v.w;
        }
    }
    int beg = ptr_at(n), end = ptr_at(n + 1);
    int i = beg;
    for (; i + 4 <= end; i += 4) {
        int sj[4];
#pragma unroll
        for (int j = 0; j < 4; j++) sj[j] = __ldg(&g_csr[i + j]);
        float4 rows[4][4];
#pragma unroll
        for (int j = 0; j < 4; j++) {
            const float4* q0 = (const float4*)(g_h1 + (size_t)sj[j] * 16);
#pragma unroll
            for (int q = 0; q < 4; q++) rows[j][q] = __ldg(&q0[q]);
        }
#pragma unroll
        for (int j = 0; j < 4; j++)
#pragma unroll
            for (int q = 0; q < 4; q++) {
                acc[4 * q + 0] += rows[j][q].x;
                acc[4 * q + 1] += rows[j][q].y;
                acc[4 * q + 2] += rows[j][q].z;
                acc[4 * q + 3] += rows[j][q].w;
            }
    }
    for (; i < end; i++) {
        int s0 = __ldg(&g_csr[i]);
        const float4* q0 = (const float4*)(g_h1 + (size_t)s0 * 16);
#pragma unroll
        for (int q = 0; q < 4; q++) {
            float4 a = __ldg(&q0[q]);
            acc[4 * q + 0] += a.x;
            acc[4 * q + 1] += a.y;
            acc[4 * q + 2] += a.z;
            acc[4 * q + 3] += a.w;
        }
    }
    // pre-act = di*acc + b1 ; relu ; @W2 ; store hs2 = h*di
    float v[16];
#pragma unroll
    for (int k = 0; k < 16; k++) v[k] = fmaxf(fmaf(di, acc[k], sW[112 + k]), 0.f);
    float h[7];
#pragma unroll
    for (int j = 0; j < 7; j++) {
        float s = 0.f;
#pragma unroll
        for (int k = 0; k < 16; k++) s += v[k] * sW[k * 7 + j];
        h[j] = s * di;
    }
    float4* hp = (float4*)(g_h2 + (size_t)n * 8);
    hp[0] = make_float4(h[0], h[1], h[2], h[3]);
    hp[1] = make_float4(h[4], h[5], h[6], 0.f);
}

// -------- layer 2 aggregate (pure gather-sum of hs2), writes d_out --------
__global__ void __launch_bounds__(256) k_agg2(const float* __restrict__ b2,
                                              float* __restrict__ out) {
    int n = blockIdx.x * blockDim.x + threadIdx.x;
    if (n >= N_NODES) return;
    float di = g_dinv[n];
    float acc[7];
    {
        const float4* hp = (const float4*)(g_h2 + (size_t)n * 8);
        float4 a = hp[0], b = hp[1];
        acc[0] = a.x; acc[1] = a.y; acc[2] = a.z; acc[3] = a.w;
        acc[4] = b.x; acc[5] = b.y; acc[6] = b.z;
    }
    int beg = ptr_at(n), end = ptr_at(n + 1);
    int i = beg;
    for (; i + 4 <= end; i += 4) {
        int sj[4];
#pragma unroll
        for (int j = 0; j < 4; j++) sj[j] = __ldg(&g_csr[i + j]);
        float4 r0[4], r1[4];
#pragma unroll
        for (int j = 0; j < 4; j++) {
            const float4* p0 = (const float4*)(g_h2 + (size_t)sj[j] * 8);
            r0[j] = __ldg(&p0[0]);
            r1[j] = __ldg(&p0[1]);
        }
#pragma unroll
        for (int j = 0; j < 4; j++) {
            acc[0] += r0[j].x;
            acc[1] += r0[j].y;
            acc[2] += r0[j].z;
            acc[3] += r0[j].w;
            acc[4] += r1[j].x;
            acc[5] += r1[j].y;
            acc[6] += r1[j].z;
        }
    }
    for (; i < end; i++) {
        int s0 = __ldg(&g_csr[i]);
        const float4* p0 = (const float4*)(g_h2 + (size_t)s0 * 8);
        float4 a0 = __ldg(&p0[0]), a1 = __ldg(&p0[1]);
        acc[0] += a0.x;
        acc[1] += a0.y;
        acc[2] += a0.z;
        acc[3] += a0.w;
        acc[4] += a1.x;
        acc[5] += a1.y;
        acc[6] += a1.z;
    }
    float* op = out + (size_t)n * 7;
#pragma unroll
    for (int j = 0; j < 7; j++) op[j] = fmaf(di, acc[j], __ldg(b2 + j));
}

extern "C" void kernel_launch(void* const* d_in, const int* in_sizes, int n_in,
                              void* d_out, int out_size) {
    const float* x  = (const float*)d_in[0];
    const void*  ei = d_in[1];
    const float* W1 = (const float*)d_in[2];
    const float* b1 = (const float*)d_in[3];
    const float* W2 = (const float*)d_in[4];
    const float* b2 = (const float*)d_in[5];
    int E = in_sizes[1] / 2;

    k_init<<<(N_NODES + 255) / 256, 256>>>((const unsigned int*)ei);  // 0
    k_convert<<<(E + 255) / 256, 256>>>(ei, E);                        // 1
    k_scan1<<<SCAN_G, SCAN_B>>>();                                     // 2
    k_gemm1<<<(N_NODES + 255) / 256, 256>>>(x, W1);                    // 3 <- profiled
    k_scan2<<<1, 128>>>();                                             // 4
    k_scatter<<<(E + 255) / 256, 256>>>(E);                            // 5
    k_agg1x<<<(N_NODES + 255) / 256, 256>>>(b1, W2);                   // 6
    k_agg2<<<(N_NODES + 255) / 256, 256>>>(b2, (float*)d_out);         // 7
}